// round 11
// baseline (speedup 1.0000x reference)
#include <cuda_runtime.h>

#define H      512
#define NC     64
#define NS     5
#define NQ     15
#define NROWS  1280

__device__ float g_att[NROWS * H];

__device__ __forceinline__ float ex2f(float x) {
    float y;
    asm("ex2.approx.f32 %0, %1;" : "=f"(y) : "f"(x));
    return y;
}
__device__ __forceinline__ float rcpf(float x) {
    float y;
    asm("rcp.approx.f32 %0, %1;" : "=f"(y) : "f"(x));
    return y;
}

// ---------------------------------------------------------------------------
// Kernel 1 (FROZEN): g_att = X @ W^T + b
// 64(m) x 32(n) tile, 128 threads, 4x4 micro-tile, BK=16.
// ---------------------------------------------------------------------------
__global__ __launch_bounds__(128) void gemm_xwt(const float* __restrict__ X,
                                                const float* __restrict__ W,
                                                const float* __restrict__ bias) {
    __shared__ float As[16][68];
    __shared__ float Bs[16][36];
    const int t  = threadIdx.x;
    const int tx = t & 7;
    const int ty = t >> 3;
    const int m0 = blockIdx.y * 64;
    const int n0 = blockIdx.x * 32;
    const int lr = t >> 2;
    const int lk = (t & 3) << 2;

    float acc[4][4] = {};

    for (int kk = 0; kk < H; kk += 16) {
        float4 a0 = *(const float4*)&X[(m0 + lr) * H + kk + lk];
        float4 a1 = *(const float4*)&X[(m0 + lr + 32) * H + kk + lk];
        float4 bv = *(const float4*)&W[(n0 + lr) * H + kk + lk];
        As[lk + 0][lr] = a0.x; As[lk + 1][lr] = a0.y;
        As[lk + 2][lr] = a0.z; As[lk + 3][lr] = a0.w;
        As[lk + 0][lr + 32] = a1.x; As[lk + 1][lr + 32] = a1.y;
        As[lk + 2][lr + 32] = a1.z; As[lk + 3][lr + 32] = a1.w;
        Bs[lk + 0][lr] = bv.x; Bs[lk + 1][lr] = bv.y;
        Bs[lk + 2][lr] = bv.z; Bs[lk + 3][lr] = bv.w;
        __syncthreads();
        #pragma unroll
        for (int k = 0; k < 16; k++) {
            float4 a4 = *(const float4*)&As[k][ty << 2];
            float4 b4 = *(const float4*)&Bs[k][tx << 2];
            float ar[4] = {a4.x, a4.y, a4.z, a4.w};
            float br[4] = {b4.x, b4.y, b4.z, b4.w};
            #pragma unroll
            for (int i = 0; i < 4; i++)
                #pragma unroll
                for (int j = 0; j < 4; j++)
                    acc[i][j] = fmaf(ar[i], br[j], acc[i][j]);
        }
        __syncthreads();
    }

    #pragma unroll
    for (int i = 0; i < 4; i++) {
        const int r = m0 + (ty << 2) + i;
        #pragma unroll
        for (int j = 0; j < 4; j++) {
            const int n = n0 + (tx << 2) + j;
            g_att[r * H + n] = acc[i][j] + bias[n];
        }
    }
}

// ---------------------------------------------------------------------------
// Kernel 2: R8 structure, but tanh computed as 1 - 2/(1+e^{2x}) with
// rt-8 EX2 ops and ONE rt-8 RCP shared across the 4 elements of a float4:
// MUFU cost 40 cyc / 4 elems vs 64 for MUFU.TANH (rt16).
// sA is pre-scaled by 2*log2(e) so EX2(a*b) = e^{2ab} with no extra FMULs.
// Sum identity: sum_h tanh = 512 - 2*sum_h u, u = 1/(1+e^{2x}).
// ---------------------------------------------------------------------------
__global__ __launch_bounds__(256, 2) void proto_attn(const float* __restrict__ X,
                                                     float* __restrict__ out) {
    const int c    = blockIdx.x;
    const int qb   = blockIdx.y;
    const int t    = threadIdx.x;
    const int warp = t >> 5;
    const int lane = t & 31;

    __shared__ float4 sA[NS * 128];   // s_att rows of class c, scaled by 2*log2(e)
    __shared__ float4 sS[NS * 128];   // raw support rows of class c

    const float4* attv = (const float4*)g_att;
    const float4* xv   = (const float4*)X;

    const float SCL = 2.8853900817779268f;   // 2 * log2(e)

    for (int i = t; i < NS * 128; i += 256) {
        const int s   = i >> 7;
        const int off = i & 127;
        const int row = c * 20 + s;
        const float4 v = attv[row * 128 + off];
        sA[i] = make_float4(v.x * SCL, v.y * SCL, v.z * SCL, v.w * SCL);
        sS[i] = xv[row * 128 + off];
    }
    __syncthreads();

    const int qc = qb * 8 + warp;

    for (int j = 0; j < NQ; j++) {
        const int row = qc * 20 + NS + j;
        const float4* qa = attv + row * 128;

        float accU[NS] = {0.f, 0.f, 0.f, 0.f, 0.f};
        #pragma unroll
        for (int i = 0; i < 4; i++) {
            const float4 a = qa[lane + i * 32];
            #pragma unroll
            for (int s = 0; s < NS; s++) {
                const float4 b = sA[s * 128 + lane + i * 32];
                // e^{2*q*s} via EX2 on pre-scaled operand
                const float e0 = ex2f(a.x * b.x);
                const float e1 = ex2f(a.y * b.y);
                const float e2 = ex2f(a.z * b.z);
                const float e3 = ex2f(a.w * b.w);
                const float d0 = e0 + 1.0f, d1 = e1 + 1.0f;
                const float d2 = e2 + 1.0f, d3 = e3 + 1.0f;
                const float d01 = d0 * d1, d23 = d2 * d3;
                const float r   = rcpf(d01 * d23);
                const float r01 = r * d23;            // 1/(d0*d1)
                const float r23 = r * d01;            // 1/(d2*d3)
                const float u0 = d1 * r01, u1 = d0 * r01;
                const float u2 = d3 * r23, u3 = d2 * r23;
                accU[s] += u0 + u1;
                accU[s] += u2 + u3;
            }
        }

        float acc[NS];
        #pragma unroll
        for (int s = 0; s < NS; s++) {
            float u = accU[s];
            #pragma unroll
            for (int o = 16; o > 0; o >>= 1)
                u += __shfl_xor_sync(0xffffffffu, u, o);
            acc[s] = fmaf(-2.0f, u, 512.0f);          // sum tanh = 512 - 2*sum u
        }

        // softmax over the 5 support scores
        float m = acc[0];
        #pragma unroll
        for (int s = 1; s < NS; s++) m = fmaxf(m, acc[s]);
        float w[NS];
        float sum = 0.f;
        #pragma unroll
        for (int s = 0; s < NS; s++) { w[s] = __expf(acc[s] - m); sum += w[s]; }
        const float inv = __fdividef(1.0f, sum);
        #pragma unroll
        for (int s = 0; s < NS; s++) w[s] *= inv;

        // proto & dist
        const float4* qx = xv + row * 128;
        float d = 0.f;
        #pragma unroll
        for (int i = 0; i < 4; i++) {
            const float4 qv = qx[lane + i * 32];
            float px = 0.f, py = 0.f, pz = 0.f, pw = 0.f;
            #pragma unroll
            for (int s = 0; s < NS; s++) {
                const float4 sv = sS[s * 128 + lane + i * 32];
                px = fmaf(w[s], sv.x, px);
                py = fmaf(w[s], sv.y, py);
                pz = fmaf(w[s], sv.z, pz);
                pw = fmaf(w[s], sv.w, pw);
            }
            const float dx = px - qv.x, dy = py - qv.y;
            const float dz = pz - qv.z, dw = pw - qv.w;
            d += dx * dx + dy * dy + dz * dz + dw * dw;
        }
        #pragma unroll
        for (int o = 16; o > 0; o >>= 1)
            d += __shfl_xor_sync(0xffffffffu, d, o);

        if (lane == 0) {
            const int q = qc * NQ + j;
            out[q * NC + c] = d;
        }
    }
}

extern "C" void kernel_launch(void* const* d_in, const int* in_sizes, int n_in,
                              void* d_out, int out_size) {
    const float* x = (const float*)d_in[0];
    const float* W = (const float*)d_in[1];
    const float* b = (const float*)d_in[2];
    float* out = (float*)d_out;

    gemm_xwt<<<dim3(H / 32, NROWS / 64), 128>>>(x, W, b);
    proto_attn<<<dim3(NC, 8), 256>>>(x, out);
}

// round 12
// speedup vs baseline: 1.4372x; 1.4372x over previous
#include <cuda_runtime.h>

#define H      512
#define NC     64
#define NS     5
#define NQ     15
#define NROWS  1280

__device__ float g_att[NROWS * H];

__device__ __forceinline__ float tanh_approx(float x) {
    float y;
    asm("tanh.approx.f32 %0, %1;" : "=f"(y) : "f"(x));
    return y;
}

// ---------------------------------------------------------------------------
// Kernel 1 (FROZEN): g_att = X @ W^T + b
// 64(m) x 32(n) tile, 128 threads, 4x4 micro-tile, BK=16.
// ---------------------------------------------------------------------------
__global__ __launch_bounds__(128) void gemm_xwt(const float* __restrict__ X,
                                                const float* __restrict__ W,
                                                const float* __restrict__ bias) {
    __shared__ float As[16][68];
    __shared__ float Bs[16][36];
    const int t  = threadIdx.x;
    const int tx = t & 7;
    const int ty = t >> 3;
    const int m0 = blockIdx.y * 64;
    const int n0 = blockIdx.x * 32;
    const int lr = t >> 2;
    const int lk = (t & 3) << 2;

    float acc[4][4] = {};

    for (int kk = 0; kk < H; kk += 16) {
        float4 a0 = *(const float4*)&X[(m0 + lr) * H + kk + lk];
        float4 a1 = *(const float4*)&X[(m0 + lr + 32) * H + kk + lk];
        float4 bv = *(const float4*)&W[(n0 + lr) * H + kk + lk];
        As[lk + 0][lr] = a0.x; As[lk + 1][lr] = a0.y;
        As[lk + 2][lr] = a0.z; As[lk + 3][lr] = a0.w;
        As[lk + 0][lr + 32] = a1.x; As[lk + 1][lr + 32] = a1.y;
        As[lk + 2][lr + 32] = a1.z; As[lk + 3][lr + 32] = a1.w;
        Bs[lk + 0][lr] = bv.x; Bs[lk + 1][lr] = bv.y;
        Bs[lk + 2][lr] = bv.z; Bs[lk + 3][lr] = bv.w;
        __syncthreads();
        #pragma unroll
        for (int k = 0; k < 16; k++) {
            float4 a4 = *(const float4*)&As[k][ty << 2];
            float4 b4 = *(const float4*)&Bs[k][tx << 2];
            float ar[4] = {a4.x, a4.y, a4.z, a4.w};
            float br[4] = {b4.x, b4.y, b4.z, b4.w};
            #pragma unroll
            for (int i = 0; i < 4; i++)
                #pragma unroll
                for (int j = 0; j < 4; j++)
                    acc[i][j] = fmaf(ar[i], br[j], acc[i][j]);
        }
        __syncthreads();
    }

    #pragma unroll
    for (int i = 0; i < 4; i++) {
        const int r = m0 + (ty << 2) + i;
        #pragma unroll
        for (int j = 0; j < 4; j++) {
            const int n = n0 + (tx << 2) + j;
            g_att[r * H + n] = acc[i][j] + bias[n];
        }
    }
}

// ---------------------------------------------------------------------------
// Kernel 2: R8 math (plain MUFU tanh — measured best), but 128-thread blocks
// (4 warps, one per SMSP) and grid (64, 16) = 1024 blocks. Finer scheduling
// grain cuts the per-SM block-count imbalance from 15.6% (4-vs-3.46 blocks
// of 8 warps) to 1.2% (7-vs-6.92 blocks of 4 warps), with identical
// 4-warps-per-SMSP latency hiding at 4 resident blocks.
// ---------------------------------------------------------------------------
__global__ __launch_bounds__(128, 4) void proto_attn(const float* __restrict__ X,
                                                     float* __restrict__ out) {
    const int c    = blockIdx.x;
    const int qb   = blockIdx.y;
    const int t    = threadIdx.x;
    const int warp = t >> 5;
    const int lane = t & 31;

    __shared__ float4 sA[NS * 128];   // s_att rows of class c
    __shared__ float4 sS[NS * 128];   // raw support rows of class c

    const float4* attv = (const float4*)g_att;
    const float4* xv   = (const float4*)X;

    for (int i = t; i < NS * 128; i += 128) {
        const int s   = i >> 7;
        const int off = i & 127;
        const int row = c * 20 + s;
        sA[i] = attv[row * 128 + off];
        sS[i] = xv[row * 128 + off];
    }
    __syncthreads();

    const int qc = qb * 4 + warp;     // 16 groups x 4 warps = 64 query-classes

    for (int j = 0; j < NQ; j++) {
        const int row = qc * 20 + NS + j;
        const float4* qa = attv + row * 128;

        float acc[NS] = {0.f, 0.f, 0.f, 0.f, 0.f};
        #pragma unroll
        for (int i = 0; i < 4; i++) {
            const float4 a = qa[lane + i * 32];
            #pragma unroll
            for (int s = 0; s < NS; s++) {
                const float4 b = sA[s * 128 + lane + i * 32];
                acc[s] += tanh_approx(a.x * b.x);
                acc[s] += tanh_approx(a.y * b.y);
                acc[s] += tanh_approx(a.z * b.z);
                acc[s] += tanh_approx(a.w * b.w);
            }
        }
        #pragma unroll
        for (int s = 0; s < NS; s++) {
            #pragma unroll
            for (int o = 16; o > 0; o >>= 1)
                acc[s] += __shfl_xor_sync(0xffffffffu, acc[s], o);
        }

        // softmax over the 5 support scores
        float m = acc[0];
        #pragma unroll
        for (int s = 1; s < NS; s++) m = fmaxf(m, acc[s]);
        float w[NS];
        float sum = 0.f;
        #pragma unroll
        for (int s = 0; s < NS; s++) { w[s] = __expf(acc[s] - m); sum += w[s]; }
        const float inv = __fdividef(1.0f, sum);
        #pragma unroll
        for (int s = 0; s < NS; s++) w[s] *= inv;

        // proto & dist
        const float4* qx = xv + row * 128;
        float d = 0.f;
        #pragma unroll
        for (int i = 0; i < 4; i++) {
            const float4 qv = qx[lane + i * 32];
            float px = 0.f, py = 0.f, pz = 0.f, pw = 0.f;
            #pragma unroll
            for (int s = 0; s < NS; s++) {
                const float4 sv = sS[s * 128 + lane + i * 32];
                px = fmaf(w[s], sv.x, px);
                py = fmaf(w[s], sv.y, py);
                pz = fmaf(w[s], sv.z, pz);
                pw = fmaf(w[s], sv.w, pw);
            }
            const float dx = px - qv.x, dy = py - qv.y;
            const float dz = pz - qv.z, dw = pw - qv.w;
            d += dx * dx + dy * dy + dz * dz + dw * dw;
        }
        #pragma unroll
        for (int o = 16; o > 0; o >>= 1)
            d += __shfl_xor_sync(0xffffffffu, d, o);

        if (lane == 0) {
            const int q = qc * NQ + j;
            out[q * NC + c] = d;
        }
    }
}

extern "C" void kernel_launch(void* const* d_in, const int* in_sizes, int n_in,
                              void* d_out, int out_size) {
    const float* x = (const float*)d_in[0];
    const float* W = (const float*)d_in[1];
    const float* b = (const float*)d_in[2];
    float* out = (float*)d_out;

    gemm_xwt<<<dim3(H / 32, NROWS / 64), 128>>>(x, W, b);
    proto_attn<<<dim3(NC, 16), 128>>>(x, out);
}